// round 10
// baseline (speedup 1.0000x reference)
#include <cuda_runtime.h>

// B=32, S=12, F=128, K=8, H=64, C=64, N=512
#define BB    32
#define SEQ   12
#define FF    128
#define KK    8
#define HH    64
#define CC    64
#define NNN   512
#define NCONS 256                    // consumer blocks: (b,k) stage1 AND (cp,p) Wf
#define NST2  32                     // stage-2 blocks (one batch each)
#define NBLK  (NCONS + NST2)         // 288 <= 296 resident slots @ 2/SM
#define TPB   256

// Scratch + sync (allocation-free rule: __device__ globals)
__device__ float g_hcat[BB * KK * HH];    // 32 x 512 elu(Wh_row)
__device__ float g_WhO[BB * CC];          // 32 x 64
__device__ unsigned int g_tick = 0;       // epoch tickets (monotonic across replays)
__device__ unsigned int g_d1 = 0;         // stage-1 done count
__device__ unsigned int g_d2 = 0;         // stage-2 done count

__device__ __forceinline__ void spin_until(volatile unsigned int* p, unsigned int target)
{
    while (*p < target) { __nanosleep(32); }
}

__global__ void __launch_bounds__(TPB, 2) gat_fused(
    const float* __restrict__ x,        // (32,12,128)
    const float* __restrict__ W_heads,  // (8,128,64)
    const float* __restrict__ W_out,    // (512,64)
    const float* __restrict__ Wf,       // (64, 512*64)
    const float* __restrict__ bf,       // (64,)
    float* __restrict__ out)            // (32,64)
{
    __shared__ float smem[3136];          // 12.5 KB, region-reused (syncs separate uses)
    __shared__ unsigned int s_epoch;      // written+read by t==0 only
    const int blk = blockIdx.x;
    const int t   = threadIdx.x;

    if (t == 0) s_epoch = atomicAdd(&g_tick, 1u) / NBLK;

    if (blk < NCONS) {
        // ========== Consumer block: stage1 (b,k) + Wf chunk (cp,p) ==========
        const int b  = blk >> 3, k = blk & 7;
        const int cp = blk >> 2, p = blk & 3;

        float* s_x = smem;                // 128 (aliases s4 region; syncs separate)
        float* s_p = smem + 128;          // 256 partials
        if (t < FF) s_x[t] = x[b * SEQ * FF + (SEQ - 1) * FF + t];

        // ---- W_heads loads FIRST (coalesced: warp spans 32 consecutive h)
        const int h  = t & 63;
        const int fg = t >> 6;            // 0..3, covers f = fg*32 .. fg*32+31
        const float* wp = W_heads + (size_t)k * FF * HH + fg * 32 * HH + h;
        float w[32];
        #pragma unroll
        for (int i = 0; i < 32; ++i) w[i] = wp[i * HH];

        // ---- Wf loads SECOND (stream under stage1 compute)
        const float4* src4 = (const float4*)(Wf + (size_t)cp * (NNN * CC) + p * (128 * CC));
        const int c4 = t & 15;
        const int nl = t >> 4;
        float4 v0 = src4[(nl      ) * 16 + c4];
        float4 v1 = src4[(nl +  16) * 16 + c4];
        float4 v2 = src4[(nl +  32) * 16 + c4];
        float4 v3 = src4[(nl +  48) * 16 + c4];
        float4 v4 = src4[(nl +  64) * 16 + c4];
        float4 v5 = src4[(nl +  80) * 16 + c4];
        float4 v6 = src4[(nl +  96) * 16 + c4];
        float4 v7 = src4[(nl + 112) * 16 + c4];

        __syncthreads();                  // s_x ready

        // ---- stage1: partial over f in [fg*32, fg*32+32)
        {
            float acc = 0.f;
            #pragma unroll
            for (int i = 0; i < 32; ++i)
                acc = fmaf(s_x[fg * 32 + i], w[i], acc);
            s_p[t] = acc;
        }
        __syncthreads();
        if (t < 64) {
            const float r = s_p[t] + s_p[t + 64] + s_p[t + 128] + s_p[t + 192];
            g_hcat[b * (KK * HH) + k * HH + t] = r > 0.f ? r : expm1f(r);
        }
        __threadfence();
        __syncthreads();
        if (t == 0) atomicAdd(&g_d1, 1u);

        // ---- Wf reduce (loads arrived / arriving)
        float4 a;
        a.x = ((v0.x + v1.x) + (v2.x + v3.x)) + ((v4.x + v5.x) + (v6.x + v7.x));
        a.y = ((v0.y + v1.y) + (v2.y + v3.y)) + ((v4.y + v5.y) + (v6.y + v7.y));
        a.z = ((v0.z + v1.z) + (v2.z + v3.z)) + ((v4.z + v5.z) + (v6.z + v7.z));
        a.w = ((v0.w + v1.w) + (v2.w + v3.w)) + ((v4.w + v5.w) + (v6.w + v7.w));

        float4* s4      = (float4*)smem;          // 256 f4 (aliases s_x/s_p; synced above)
        float*  s_wpart = smem + 1024;            // 64
        float*  s_WhO   = smem + 1088;            // 2048

        s4[t] = a;
        __syncthreads();
        if (t < 128) { float4 o = s4[t + 128]; s4[t].x += o.x; s4[t].y += o.y; s4[t].z += o.z; s4[t].w += o.w; }
        __syncthreads();
        if (t < 64)  { float4 o = s4[t + 64];  s4[t].x += o.x; s4[t].y += o.y; s4[t].z += o.z; s4[t].w += o.w; }
        __syncthreads();
        if (t < 16) {
            float4 r = s4[t];
            float4 o1 = s4[t + 16], o2 = s4[t + 32], o3 = s4[t + 48];
            s_wpart[4 * t + 0] = r.x + o1.x + o2.x + o3.x;
            s_wpart[4 * t + 1] = r.y + o1.y + o2.y + o3.y;
            s_wpart[4 * t + 2] = r.z + o1.z + o2.z + o3.z;
            s_wpart[4 * t + 3] = r.w + o1.w + o2.w + o3.w;
        }
        __syncthreads();

        // ---- wait for all 32 stage-2 publishes of this epoch
        if (t == 0) spin_until(&g_d2, (s_epoch + 1u) * NST2);
        __syncthreads();
        __threadfence();

        // WhO -> smem (8 KB, L2-hot)
        {
            float4* d = (float4*)s_WhO;
            const float4* s = (const float4*)g_WhO;
            d[t] = s[t];
            d[t + 256] = s[t + 256];
        }
        __syncthreads();

        // contrib[b2] = sum_c WhO[b2,c]*wpart[c]; 8 threads per b2
        {
            const int b2 = t >> 3;
            const int jg = t & 7;
            float acc = 0.f;
            #pragma unroll
            for (int i = 0; i < 8; ++i) {
                const int c = jg * 8 + i;
                acc = fmaf(s_WhO[b2 * CC + c], s_wpart[c], acc);
            }
            acc += __shfl_down_sync(0xffffffffu, acc, 4);
            acc += __shfl_down_sync(0xffffffffu, acc, 2);
            acc += __shfl_down_sync(0xffffffffu, acc, 1);
            if (jg == 0) atomicAdd(&out[b2 * CC + cp], acc);
        }
    } else {
        // ========== Stage-2 block: one batch b ==========
        const int b = blk - NCONS;

        // prefetch this block's 4KB W_out slice into L2 during the spin
        // (32 blocks together cover the full 128 KB)
        {
            const float* pf = W_out + b * (NNN * CC / NST2) + t * 4;
            asm volatile("prefetch.global.L2 [%0];" :: "l"(pf));
        }
        if (t == 0) spin_until(&g_d1, (s_epoch + 1u) * NCONS);
        __syncthreads();
        __threadfence();

        float*  s_h = smem;                        // 512
        float4* s4  = (float4*)(smem + 1024);      // 256 f4

        s_h[t]       = g_hcat[b * (KK * HH) + t];
        s_h[t + 256] = g_hcat[b * (KK * HH) + 256 + t];
        __syncthreads();

        // WhO[c] = sum_j hcat[j]*W_out[j,c]; fully unrolled -> one (L2-hit) window
        const int c4 = t & 15;
        const int g  = t >> 4;
        const float4* Wo4 = (const float4*)W_out;
        float4 a = make_float4(0.f, 0.f, 0.f, 0.f);
        #pragma unroll
        for (int jl = 0; jl < 32; ++jl) {
            const int j = g * 32 + jl;
            const float4 w = Wo4[j * 16 + c4];
            const float hv = s_h[j];
            a.x = fmaf(w.x, hv, a.x); a.y = fmaf(w.y, hv, a.y);
            a.z = fmaf(w.z, hv, a.z); a.w = fmaf(w.w, hv, a.w);
        }
        s4[t] = a;
        __syncthreads();
        if (t < 128) { float4 o = s4[t + 128]; s4[t].x += o.x; s4[t].y += o.y; s4[t].z += o.z; s4[t].w += o.w; }
        __syncthreads();
        if (t < 64)  { float4 o = s4[t + 64];  s4[t].x += o.x; s4[t].y += o.y; s4[t].z += o.z; s4[t].w += o.w; }
        __syncthreads();
        if (t < 16) {
            float4 r = s4[t];
            float4 o1 = s4[t + 16], o2 = s4[t + 32], o3 = s4[t + 48];
            r.x += o1.x + o2.x + o3.x;
            r.y += o1.y + o2.y + o3.y;
            r.z += o1.z + o2.z + o3.z;
            r.w += o1.w + o2.w + o3.w;
            ((float4*)(g_WhO + b * CC))[t] = r;
        }
        if (t < CC) out[b * CC + t] = bf[t];      // init; consumers add on top
        __threadfence();
        __syncthreads();
        if (t == 0) atomicAdd(&g_d2, 1u);
    }
}

extern "C" void kernel_launch(void* const* d_in, const int* in_sizes, int n_in,
                              void* d_out, int out_size)
{
    const float* x       = (const float*)d_in[0];
    const float* W_heads = (const float*)d_in[1];
    // d_in[2], d_in[3]: a1_heads/a2_heads — drop out (uniform softmax)
    const float* W_out   = (const float*)d_in[4];
    // d_in[5], d_in[6]: a1_out/a2_out — drop out
    const float* Wf      = (const float*)d_in[7];
    const float* bf      = (const float*)d_in[8];
    float* out           = (float*)d_out;

    gat_fused<<<NBLK, TPB>>>(x, W_heads, W_out, Wf, bf, out);
}